// round 1
// baseline (speedup 1.0000x reference)
#include <cuda_runtime.h>
#include <cstdint>

#define N_ROWS 100000
#define IN_CH  256
#define OUT_CH 128
#define KVOL   8

#define BM 128
#define BN 128
#define BK 16
#define APAD 20    // A smem row stride (floats): g*20+l4 conflict-free mod 32
#define NPAD 136   // B smem row stride (floats): l4*8+g conflict-free mod 32

__device__ __forceinline__ uint32_t f2tf32(float x) {
    uint32_t u;
    asm("cvt.rna.tf32.f32 %0, %1;" : "=r"(u) : "f"(x));
    return u;
}

__global__ __launch_bounds__(256)
void gemm_tf32_kernel(const float* __restrict__ A,
                      const float* __restrict__ W,
                      float* __restrict__ out)
{
    __shared__ uint32_t As[2][BM][APAD];
    __shared__ uint32_t Bs[2][BK][NPAD];

    const int tid = threadIdx.x;
    const int kb  = blockIdx.x;           // kernel offset 0..7 -> B = W[kb]
    const int m0  = blockIdx.y * BM;
    const float* Bw = W + (size_t)kb * IN_CH * OUT_CH;   // [256,128] row-major

    // staging thread mapping
    const int ar = tid >> 2;              // 0..63  (A rows, +64 second half)
    const int ac = (tid & 3) * 4;         // 0,4,8,12
    const int bk = tid >> 5;              // 0..7   (B k-rows, +8 second half)
    const int bn = (tid & 31) * 4;        // 0..124

    // warp mapping: 8 warps = 4 (M) x 2 (N); each warp 32x64
    const int lane = tid & 31;
    const int wid  = tid >> 5;
    const int wm = (wid >> 1) * 32;
    const int wn = (wid & 1) * 64;
    const int g  = lane >> 2;
    const int l4 = lane & 3;

    float4 ra0, ra1, rb0, rb1;

    auto load_tile = [&](int k0) {
        const int r0 = m0 + ar;
        const int r1 = m0 + ar + 64;
        ra0 = (r0 < N_ROWS) ? *(const float4*)(A + (size_t)r0 * IN_CH + k0 + ac)
                            : make_float4(0.f, 0.f, 0.f, 0.f);
        ra1 = (r1 < N_ROWS) ? *(const float4*)(A + (size_t)r1 * IN_CH + k0 + ac)
                            : make_float4(0.f, 0.f, 0.f, 0.f);
        rb0 = *(const float4*)(Bw + (size_t)(k0 + bk)     * OUT_CH + bn);
        rb1 = *(const float4*)(Bw + (size_t)(k0 + bk + 8) * OUT_CH + bn);
    };

    auto stage = [&](int buf) {
        uint32_t* pa0 = &As[buf][ar][ac];
        pa0[0] = f2tf32(ra0.x); pa0[1] = f2tf32(ra0.y);
        pa0[2] = f2tf32(ra0.z); pa0[3] = f2tf32(ra0.w);
        uint32_t* pa1 = &As[buf][ar + 64][ac];
        pa1[0] = f2tf32(ra1.x); pa1[1] = f2tf32(ra1.y);
        pa1[2] = f2tf32(ra1.z); pa1[3] = f2tf32(ra1.w);
        uint32_t* pb0 = &Bs[buf][bk][bn];
        pb0[0] = f2tf32(rb0.x); pb0[1] = f2tf32(rb0.y);
        pb0[2] = f2tf32(rb0.z); pb0[3] = f2tf32(rb0.w);
        uint32_t* pb1 = &Bs[buf][bk + 8][bn];
        pb1[0] = f2tf32(rb1.x); pb1[1] = f2tf32(rb1.y);
        pb1[2] = f2tf32(rb1.z); pb1[3] = f2tf32(rb1.w);
    };

    float acc[2][8][4];
    #pragma unroll
    for (int mt = 0; mt < 2; ++mt)
        #pragma unroll
        for (int nt = 0; nt < 8; ++nt)
            #pragma unroll
            for (int i = 0; i < 4; ++i)
                acc[mt][nt][i] = 0.f;

    auto compute = [&](int buf) {
        #pragma unroll
        for (int ks = 0; ks < 2; ++ks) {
            const int kk = ks * 8;
            uint32_t af[2][4];
            #pragma unroll
            for (int mt = 0; mt < 2; ++mt) {
                const int r = wm + mt * 16 + g;
                af[mt][0] = As[buf][r][kk + l4];
                af[mt][1] = As[buf][r + 8][kk + l4];
                af[mt][2] = As[buf][r][kk + l4 + 4];
                af[mt][3] = As[buf][r + 8][kk + l4 + 4];
            }
            #pragma unroll
            for (int nt = 0; nt < 8; ++nt) {
                const int c = wn + nt * 8 + g;
                const uint32_t b0 = Bs[buf][kk + l4][c];
                const uint32_t b1 = Bs[buf][kk + l4 + 4][c];
                #pragma unroll
                for (int mt = 0; mt < 2; ++mt) {
                    asm volatile(
                        "mma.sync.aligned.m16n8k8.row.col.f32.tf32.tf32.f32 "
                        "{%0,%1,%2,%3}, {%4,%5,%6,%7}, {%8,%9}, {%0,%1,%2,%3};\n"
                        : "+f"(acc[mt][nt][0]), "+f"(acc[mt][nt][1]),
                          "+f"(acc[mt][nt][2]), "+f"(acc[mt][nt][3])
                        : "r"(af[mt][0]), "r"(af[mt][1]),
                          "r"(af[mt][2]), "r"(af[mt][3]),
                          "r"(b0), "r"(b1));
                }
            }
        }
    };

    load_tile(0);
    #pragma unroll 1
    for (int kt = 0; kt < IN_CH / BK; ++kt) {
        const int buf = kt & 1;
        stage(buf);
        __syncthreads();
        if (kt + 1 < IN_CH / BK) load_tile((kt + 1) * BK);
        compute(buf);
        // no second sync: double buffer + the next iteration's __syncthreads()
        // guarantees compute(kt-1) is done before buf is overwritten at kt+1.
    }

    // epilogue: out[(n*8 + kb)*128 + col]
    #pragma unroll
    for (int mt = 0; mt < 2; ++mt) {
        const int r0 = m0 + wm + mt * 16 + g;
        const int r1 = r0 + 8;
        #pragma unroll
        for (int nt = 0; nt < 8; ++nt) {
            const int c = wn + nt * 8 + l4 * 2;
            if (r0 < N_ROWS) {
                float2 v = make_float2(acc[mt][nt][0], acc[mt][nt][1]);
                *(float2*)(out + ((size_t)r0 * KVOL + kb) * OUT_CH + c) = v;
            }
            if (r1 < N_ROWS) {
                float2 v = make_float2(acc[mt][nt][2], acc[mt][nt][3]);
                *(float2*)(out + ((size_t)r1 * KVOL + kb) * OUT_CH + c) = v;
            }
        }
    }
}

__global__ void coords_kernel(const int* __restrict__ coords, float* __restrict__ out)
{
    const long long total = (long long)N_ROWS * KVOL * 3;
    long long i = (long long)blockIdx.x * blockDim.x + threadIdx.x;
    if (i >= total) return;
    const int j = (int)(i % 3);
    const long long t = i / 3;
    const int k = (int)(t % KVOL);
    const long long n = t / KVOL;
    const int off = (k >> (2 - j)) & 1;
    out[i] = (float)(2 * coords[n * 3 + j] + off);
}

extern "C" void kernel_launch(void* const* d_in, const int* in_sizes, int n_in,
                              void* d_out, int out_size)
{
    const float* feats  = nullptr;
    const int*   coords = nullptr;
    const float* W      = nullptr;
    for (int i = 0; i < n_in; ++i) {
        if      (in_sizes[i] == N_ROWS * IN_CH)        feats  = (const float*)d_in[i];
        else if (in_sizes[i] == N_ROWS * 3)            coords = (const int*)d_in[i];
        else if (in_sizes[i] == KVOL * IN_CH * OUT_CH) W      = (const float*)d_in[i];
    }
    float* out = (float*)d_out;

    dim3 grid(KVOL, (N_ROWS + BM - 1) / BM);   // kb fastest: 8 CTAs share A tile in L2
    gemm_tf32_kernel<<<grid, 256>>>(feats, W, out);

    const long long featsN = (long long)N_ROWS * KVOL * OUT_CH;   // 102,400,000
    const long long coordN = (long long)N_ROWS * KVOL * 3;        //   2,400,000
    if ((long long)out_size >= featsN + coordN && coords != nullptr) {
        const int threads = 256;
        const int blocks = (int)((coordN + threads - 1) / threads);
        coords_kernel<<<blocks, threads>>>(coords, out + featsN);
    }
}